// round 2
// baseline (speedup 1.0000x reference)
#include <cuda_runtime.h>
#include <math.h>

#define T_TOK 1024
#define H_DIM 2048
#define I_DIM 768
#define E_NUM 32
#define K_TOP 8

#define BM 64
#define BN 64
#define BK 16

// ---------------- scratch (static device globals; no runtime allocation) ----------------
__device__ int   g_cnt[E_NUM];
__device__ int   g_off[E_NUM + 1];
__device__ int   g_list_tok[E_NUM * T_TOK];
__device__ float g_list_w[E_NUM * T_TOK];
__device__ int   g_list_tk[E_NUM * T_TOK];
__device__ int   g_slot_of[T_TOK * K_TOP];
__device__ float g_act[(size_t)T_TOK * K_TOP * I_DIM];    // 25.2 MB
__device__ float g_pair[(size_t)T_TOK * K_TOP * H_DIM];   // 67 MB

__global__ void zero_cnt_kernel() {
    if (threadIdx.x < E_NUM) g_cnt[threadIdx.x] = 0;
}

// ---------------- router: logits, softmax, top-8, normalized weights, expert lists ----------------
__global__ void router_kernel(const float* __restrict__ x,
                              const float* __restrict__ gate_w,
                              float* __restrict__ logits_out) {
    const int TPB = 4;  // tokens per block
    __shared__ float xs[TPB][H_DIM];
    __shared__ float lg[TPB][E_NUM];

    int t0 = blockIdx.x * TPB;

    // cooperative load of 4 token rows (float4)
    const float4* xv  = (const float4*)(x + (size_t)t0 * H_DIM);
    float4*       xsv = (float4*)&xs[0][0];
    for (int i = threadIdx.x; i < TPB * H_DIM / 4; i += blockDim.x) xsv[i] = xv[i];
    __syncthreads();

    int warp = threadIdx.x >> 5;
    int lane = threadIdx.x & 31;

    // 8 warps x 4 experts each = 32 experts; coalesced gate_w reads, reused across 4 tokens
    for (int sub = 0; sub < 4; sub++) {
        int e = warp + sub * 8;
        const float* w = gate_w + (size_t)e * H_DIM;
        float p0 = 0.f, p1 = 0.f, p2 = 0.f, p3 = 0.f;
        for (int h = lane; h < H_DIM; h += 32) {
            float wv = w[h];
            p0 += xs[0][h] * wv;
            p1 += xs[1][h] * wv;
            p2 += xs[2][h] * wv;
            p3 += xs[3][h] * wv;
        }
        for (int o = 16; o; o >>= 1) {
            p0 += __shfl_xor_sync(0xFFFFFFFFu, p0, o);
            p1 += __shfl_xor_sync(0xFFFFFFFFu, p1, o);
            p2 += __shfl_xor_sync(0xFFFFFFFFu, p2, o);
            p3 += __shfl_xor_sync(0xFFFFFFFFu, p3, o);
        }
        if (lane == 0) { lg[0][e] = p0; lg[1][e] = p1; lg[2][e] = p2; lg[3][e] = p3; }
    }
    __syncthreads();

    if (warp < TPB) {
        int t = t0 + warp;
        float logit = lg[warp][lane];
        if (logits_out) logits_out[(size_t)t * E_NUM + lane] = logit;

        // softmax over 32 experts (one lane per expert)
        float m = logit;
        for (int o = 16; o; o >>= 1) m = fmaxf(m, __shfl_xor_sync(0xFFFFFFFFu, m, o));
        float ex = expf(logit - m);
        float s = ex;
        for (int o = 16; o; o >>= 1) s += __shfl_xor_sync(0xFFFFFFFFu, s, o);
        float prob = ex / s;

        // top-8 by iterative warp argmax
        float v = prob;
        float wsum = 0.f;
        float selw[K_TOP];
        int   sele[K_TOP];
#pragma unroll
        for (int k = 0; k < K_TOP; k++) {
            float mv = v;
            for (int o = 16; o; o >>= 1) mv = fmaxf(mv, __shfl_xor_sync(0xFFFFFFFFu, mv, o));
            unsigned msk = __ballot_sync(0xFFFFFFFFu, v == mv);
            int src = __ffs(msk) - 1;
            if (lane == 0) { sele[k] = src; selw[k] = mv; wsum += mv; }
            if (lane == src) v = -1.f;
        }
        if (lane == 0) {
#pragma unroll
            for (int k = 0; k < K_TOP; k++) {
                int e = sele[k];
                float wn = selw[k] / wsum;
                int pos = atomicAdd(&g_cnt[e], 1);
                g_list_tok[e * T_TOK + pos] = t;
                g_list_w[e * T_TOK + pos]   = wn;
                g_list_tk[e * T_TOK + pos]  = t * K_TOP + k;
            }
        }
    }
}

// ---------------- exclusive scan of expert counts ----------------
__global__ void scan_kernel() {
    if (threadIdx.x == 0) {
        int acc = 0;
        for (int e = 0; e < E_NUM; e++) { g_off[e] = acc; acc += g_cnt[e]; }
        g_off[E_NUM] = acc;
    }
}

// ---------------- fill token->slot reverse map ----------------
__global__ void remap_kernel() {
    int e = blockIdx.x;
    int n = g_cnt[e], o = g_off[e];
    for (int p = threadIdx.x; p < n; p += blockDim.x)
        g_slot_of[g_list_tk[e * T_TOK + p]] = o + p;
}

__device__ __forceinline__ float silu_f(float g) { return g / (1.f + expf(-g)); }

// ---------------- grouped gate+up GEMM + SiLU epilogue ----------------
// C[m][n] = sum_h X[tok_m][h] * W[n][h], for both gate and up weights; X tile shared.
__global__ __launch_bounds__(256) void gateup_kernel(const float* __restrict__ x,
                                                     const float* __restrict__ gw,
                                                     const float* __restrict__ uw) {
    int e  = blockIdx.z;
    int n  = g_cnt[e];
    int m0 = blockIdx.x * BM;
    if (m0 >= n) return;
    int c0 = blockIdx.y * BN;

    __shared__ float As[BK][BM + 4];
    __shared__ float Bg[BK][BN + 4];
    __shared__ float Bu[BK][BN + 4];

    int tid = threadIdx.x;
    int r  = tid >> 2;          // 0..63  (tile row for loading)
    int kq = (tid & 3) << 2;    // 0,4,8,12

    int mrow = m0 + r;
    int tokc = g_list_tok[e * T_TOK + min(mrow, n - 1)];
    const float* arow = x  + (size_t)tokc * H_DIM;
    const float* grow = gw + ((size_t)e * I_DIM + (c0 + r)) * H_DIM;
    const float* urow = uw + ((size_t)e * I_DIM + (c0 + r)) * H_DIM;

    int tx = tid & 15;   // n-dir
    int ty = tid >> 4;   // m-dir

    float cg[4][4] = {};
    float cu[4][4] = {};

    for (int h0 = 0; h0 < H_DIM; h0 += BK) {
        float4 av = *(const float4*)(arow + h0 + kq);
        float4 gv = *(const float4*)(grow + h0 + kq);
        float4 uv = *(const float4*)(urow + h0 + kq);
        __syncthreads();
        As[kq + 0][r] = av.x; As[kq + 1][r] = av.y; As[kq + 2][r] = av.z; As[kq + 3][r] = av.w;
        Bg[kq + 0][r] = gv.x; Bg[kq + 1][r] = gv.y; Bg[kq + 2][r] = gv.z; Bg[kq + 3][r] = gv.w;
        Bu[kq + 0][r] = uv.x; Bu[kq + 1][r] = uv.y; Bu[kq + 2][r] = uv.z; Bu[kq + 3][r] = uv.w;
        __syncthreads();
#pragma unroll
        for (int kk = 0; kk < BK; kk++) {
            float4 a4 = *(const float4*)&As[kk][ty * 4];
            float4 g4 = *(const float4*)&Bg[kk][tx * 4];
            float4 u4 = *(const float4*)&Bu[kk][tx * 4];
            float aa[4] = {a4.x, a4.y, a4.z, a4.w};
            float bg[4] = {g4.x, g4.y, g4.z, g4.w};
            float bu[4] = {u4.x, u4.y, u4.z, u4.w};
#pragma unroll
            for (int im = 0; im < 4; im++)
#pragma unroll
                for (int in = 0; in < 4; in++) {
                    cg[im][in] += aa[im] * bg[in];
                    cu[im][in] += aa[im] * bu[in];
                }
        }
    }

    int off = g_off[e];
#pragma unroll
    for (int im = 0; im < 4; im++) {
        int row = m0 + ty * 4 + im;
        if (row < n) {
            float wv = g_list_w[e * T_TOK + row];
            float4 o;
            o.x = silu_f(cg[im][0]) * cu[im][0] * wv;
            o.y = silu_f(cg[im][1]) * cu[im][1] * wv;
            o.z = silu_f(cg[im][2]) * cu[im][2] * wv;
            o.w = silu_f(cg[im][3]) * cu[im][3] * wv;
            *(float4*)&g_act[((size_t)(off + row)) * I_DIM + c0 + tx * 4] = o;
        }
    }
}

// ---------------- grouped down-proj GEMM ----------------
__global__ __launch_bounds__(256) void down_kernel(const float* __restrict__ dw) {
    int e  = blockIdx.z;
    int n  = g_cnt[e];
    int m0 = blockIdx.x * BM;
    if (m0 >= n) return;
    int c0  = blockIdx.y * BN;   // h-column base
    int off = g_off[e];

    __shared__ float As[BK][BM + 4];
    __shared__ float Bs[BK][BN + 4];

    int tid = threadIdx.x;
    int r  = tid >> 2;
    int kq = (tid & 3) << 2;

    int arow_idx = off + min(m0 + r, n - 1);
    const float* arow = g_act + (size_t)arow_idx * I_DIM;
    const float* brow = dw + ((size_t)e * H_DIM + (c0 + r)) * I_DIM;

    int tx = tid & 15;
    int ty = tid >> 4;
    float c[4][4] = {};

    for (int k0 = 0; k0 < I_DIM; k0 += BK) {
        float4 av = *(const float4*)(arow + k0 + kq);
        float4 bv = *(const float4*)(brow + k0 + kq);
        __syncthreads();
        As[kq + 0][r] = av.x; As[kq + 1][r] = av.y; As[kq + 2][r] = av.z; As[kq + 3][r] = av.w;
        Bs[kq + 0][r] = bv.x; Bs[kq + 1][r] = bv.y; Bs[kq + 2][r] = bv.z; Bs[kq + 3][r] = bv.w;
        __syncthreads();
#pragma unroll
        for (int kk = 0; kk < BK; kk++) {
            float4 a4 = *(const float4*)&As[kk][ty * 4];
            float4 b4 = *(const float4*)&Bs[kk][tx * 4];
            float aa[4] = {a4.x, a4.y, a4.z, a4.w};
            float bb[4] = {b4.x, b4.y, b4.z, b4.w};
#pragma unroll
            for (int im = 0; im < 4; im++)
#pragma unroll
                for (int in = 0; in < 4; in++)
                    c[im][in] += aa[im] * bb[in];
        }
    }

#pragma unroll
    for (int im = 0; im < 4; im++) {
        int row = m0 + ty * 4 + im;
        if (row < n) {
            float4 o = make_float4(c[im][0], c[im][1], c[im][2], c[im][3]);
            *(float4*)&g_pair[((size_t)(off + row)) * H_DIM + c0 + tx * 4] = o;
        }
    }
}

// ---------------- per-token reduction over its 8 expert contributions ----------------
__global__ void reduce_kernel(float* __restrict__ out) {
    int t = blockIdx.x;
    int s[K_TOP];
#pragma unroll
    for (int k = 0; k < K_TOP; k++) s[k] = g_slot_of[t * K_TOP + k];
    const float4* base = (const float4*)g_pair;
    float4* ob = (float4*)(out + (size_t)t * H_DIM);
    for (int i = threadIdx.x; i < H_DIM / 4; i += blockDim.x) {
        float4 acc = make_float4(0.f, 0.f, 0.f, 0.f);
#pragma unroll
        for (int k = 0; k < K_TOP; k++) {
            float4 v = base[(size_t)s[k] * (H_DIM / 4) + i];
            acc.x += v.x; acc.y += v.y; acc.z += v.z; acc.w += v.w;
        }
        ob[i] = acc;
    }
}

// ---------------- launch ----------------
extern "C" void kernel_launch(void* const* d_in, const int* in_sizes, int n_in,
                              void* d_out, int out_size) {
    const float* x      = (const float*)d_in[0];  // [1,1024,2048]
    const float* gate_w = (const float*)d_in[1];  // [32,2048]
    const float* gw     = (const float*)d_in[2];  // [32,768,2048]
    const float* uw     = (const float*)d_in[3];  // [32,768,2048]
    const float* dw     = (const float*)d_in[4];  // [32,2048,768]
    float* out = (float*)d_out;

    // output tuple order: final [T,H] then router_logits [T,E]
    float* logits = (out_size >= T_TOK * H_DIM + T_TOK * E_NUM) ? (out + (size_t)T_TOK * H_DIM)
                                                                : (float*)0;

    zero_cnt_kernel<<<1, 32>>>();
    router_kernel<<<T_TOK / 4, 256>>>(x, gate_w, logits);
    scan_kernel<<<1, 32>>>();
    remap_kernel<<<E_NUM, 256>>>();
    gateup_kernel<<<dim3(T_TOK / BM, I_DIM / BN, E_NUM), 256>>>(x, gw, uw);
    down_kernel<<<dim3(T_TOK / BM, H_DIM / BN, E_NUM), 256>>>(dw);
    reduce_kernel<<<T_TOK, 256>>>(out);
}

// round 3
// speedup vs baseline: 2.5710x; 2.5710x over previous
#include <cuda_runtime.h>
#include <math.h>

#define T_TOK 1024
#define H_DIM 2048
#define I_DIM 768
#define E_NUM 32
#define K_TOP 8

// GEMM tiling
#define BM 128
#define BN 64
#define BK 32
#define BKP 36   // padded stride (floats): bank = (4*row + k) % 32 -> conflict-free frags

// ---------------- scratch ----------------
__device__ int   g_cnt[E_NUM];
__device__ int   g_off[E_NUM + 1];
__device__ int   g_list_tok[E_NUM * T_TOK];
__device__ float g_list_w[E_NUM * T_TOK];
__device__ int   g_list_tk[E_NUM * T_TOK];
__device__ int   g_slot_of[T_TOK * K_TOP];
__device__ float g_act[(size_t)T_TOK * K_TOP * I_DIM];
__device__ float g_pair[(size_t)T_TOK * K_TOP * H_DIM];

__global__ void zero_cnt_kernel() {
    if (threadIdx.x < E_NUM) g_cnt[threadIdx.x] = 0;
}

// ---------------- router ----------------
__global__ void router_kernel(const float* __restrict__ x,
                              const float* __restrict__ gate_w,
                              float* __restrict__ logits_out) {
    const int TPB = 4;
    __shared__ float xs[TPB][H_DIM];
    __shared__ float lg[TPB][E_NUM];

    int t0 = blockIdx.x * TPB;
    const float4* xv  = (const float4*)(x + (size_t)t0 * H_DIM);
    float4*       xsv = (float4*)&xs[0][0];
    for (int i = threadIdx.x; i < TPB * H_DIM / 4; i += blockDim.x) xsv[i] = xv[i];
    __syncthreads();

    int warp = threadIdx.x >> 5;
    int lane = threadIdx.x & 31;

    for (int sub = 0; sub < 4; sub++) {
        int e = warp + sub * 8;
        const float* w = gate_w + (size_t)e * H_DIM;
        float p0 = 0.f, p1 = 0.f, p2 = 0.f, p3 = 0.f;
        for (int h = lane; h < H_DIM; h += 32) {
            float wv = w[h];
            p0 += xs[0][h] * wv;
            p1 += xs[1][h] * wv;
            p2 += xs[2][h] * wv;
            p3 += xs[3][h] * wv;
        }
        for (int o = 16; o; o >>= 1) {
            p0 += __shfl_xor_sync(0xFFFFFFFFu, p0, o);
            p1 += __shfl_xor_sync(0xFFFFFFFFu, p1, o);
            p2 += __shfl_xor_sync(0xFFFFFFFFu, p2, o);
            p3 += __shfl_xor_sync(0xFFFFFFFFu, p3, o);
        }
        if (lane == 0) { lg[0][e] = p0; lg[1][e] = p1; lg[2][e] = p2; lg[3][e] = p3; }
    }
    __syncthreads();

    if (warp < TPB) {
        int t = t0 + warp;
        float logit = lg[warp][lane];
        if (logits_out) logits_out[(size_t)t * E_NUM + lane] = logit;

        float m = logit;
        for (int o = 16; o; o >>= 1) m = fmaxf(m, __shfl_xor_sync(0xFFFFFFFFu, m, o));
        float ex = expf(logit - m);
        float s = ex;
        for (int o = 16; o; o >>= 1) s += __shfl_xor_sync(0xFFFFFFFFu, s, o);
        float prob = ex / s;

        float v = prob;
        float wsum = 0.f;
        float selw[K_TOP];
        int   sele[K_TOP];
#pragma unroll
        for (int k = 0; k < K_TOP; k++) {
            float mv = v;
            for (int o = 16; o; o >>= 1) mv = fmaxf(mv, __shfl_xor_sync(0xFFFFFFFFu, mv, o));
            unsigned msk = __ballot_sync(0xFFFFFFFFu, v == mv);
            int src = __ffs(msk) - 1;
            if (lane == 0) { sele[k] = src; selw[k] = mv; wsum += mv; }
            if (lane == src) v = -1.f;
        }
        if (lane == 0) {
#pragma unroll
            for (int k = 0; k < K_TOP; k++) {
                int e = sele[k];
                float wn = selw[k] / wsum;
                int pos = atomicAdd(&g_cnt[e], 1);
                g_list_tok[e * T_TOK + pos] = t;
                g_list_w[e * T_TOK + pos]   = wn;
                g_list_tk[e * T_TOK + pos]  = t * K_TOP + k;
            }
        }
    }
}

__global__ void scan_kernel() {
    if (threadIdx.x == 0) {
        int acc = 0;
        for (int e = 0; e < E_NUM; e++) { g_off[e] = acc; acc += g_cnt[e]; }
        g_off[E_NUM] = acc;
    }
}

__global__ void remap_kernel() {
    int e = blockIdx.x;
    int n = g_cnt[e], o = g_off[e];
    for (int p = threadIdx.x; p < n; p += blockDim.x)
        g_slot_of[g_list_tk[e * T_TOK + p]] = o + p;
}

__device__ __forceinline__ float silu_f(float g) { return g / (1.f + expf(-g)); }

__device__ __forceinline__ unsigned f2tf(float f) {
    unsigned r;
    asm("cvt.rna.tf32.f32 %0, %1;" : "=r"(r) : "f"(f));
    return r;
}
__device__ __forceinline__ void cvt4(unsigned* d, float4 v) {
    d[0] = f2tf(v.x); d[1] = f2tf(v.y); d[2] = f2tf(v.z); d[3] = f2tf(v.w);
}
__device__ __forceinline__ void mma_tf32(float* c, unsigned a0, unsigned a1, unsigned a2, unsigned a3,
                                         unsigned b0, unsigned b1) {
    asm volatile("mma.sync.aligned.m16n8k8.row.col.f32.tf32.tf32.f32 "
                 "{%0,%1,%2,%3}, {%4,%5,%6,%7}, {%8,%9}, {%0,%1,%2,%3};"
                 : "+f"(c[0]), "+f"(c[1]), "+f"(c[2]), "+f"(c[3])
                 : "r"(a0), "r"(a1), "r"(a2), "r"(a3), "r"(b0), "r"(b1));
}

// ---------------- grouped gate+up GEMM (tf32 mma) + SiLU epilogue ----------------
__global__ __launch_bounds__(256) void gateup_kernel(const float* __restrict__ x,
                                                     const float* __restrict__ gw,
                                                     const float* __restrict__ uw) {
    int e  = blockIdx.z;
    int n  = g_cnt[e];
    int m0 = blockIdx.x * BM;
    if (m0 >= n) return;
    int c0 = blockIdx.y * BN;

    __shared__ unsigned As[BM * BKP];
    __shared__ unsigned Bgs[BN * BKP];
    __shared__ unsigned Bus[BN * BKP];

    int tid  = threadIdx.x;
    int lane = tid & 31;
    int warp = tid >> 5;
    int wM = warp & 3;   // 0..3
    int wN = warp >> 2;  // 0..1

    // ---- global load mapping ----
    int lr = tid >> 3;          // 0..31
    int c4 = (tid & 7) << 2;    // 0,4,..,28

    const float* aptr[4];
#pragma unroll
    for (int i = 0; i < 4; i++) {
        int row = m0 + lr + i * 32;
        int tok = g_list_tok[e * T_TOK + min(row, n - 1)];
        aptr[i] = x + (size_t)tok * H_DIM + c4;
    }
    const float* gptr0 = gw + ((size_t)e * I_DIM + (c0 + lr)) * H_DIM + c4;
    const float* gptr1 = gw + ((size_t)e * I_DIM + (c0 + lr + 32)) * H_DIM + c4;
    const float* uptr0 = uw + ((size_t)e * I_DIM + (c0 + lr)) * H_DIM + c4;
    const float* uptr1 = uw + ((size_t)e * I_DIM + (c0 + lr + 32)) * H_DIM + c4;

    float cg[2][4][4] = {};
    float cu[2][4][4] = {};

    for (int h0 = 0; h0 < H_DIM; h0 += BK) {
        float4 av[4];
#pragma unroll
        for (int i = 0; i < 4; i++) av[i] = *(const float4*)(aptr[i] + h0);
        float4 gv0 = *(const float4*)(gptr0 + h0);
        float4 gv1 = *(const float4*)(gptr1 + h0);
        float4 uv0 = *(const float4*)(uptr0 + h0);
        float4 uv1 = *(const float4*)(uptr1 + h0);

        __syncthreads();
        unsigned t4[4];
#pragma unroll
        for (int i = 0; i < 4; i++) {
            cvt4(t4, av[i]);
            *(uint4*)&As[(lr + i * 32) * BKP + c4] = *(uint4*)t4;
        }
        cvt4(t4, gv0); *(uint4*)&Bgs[lr * BKP + c4]        = *(uint4*)t4;
        cvt4(t4, gv1); *(uint4*)&Bgs[(lr + 32) * BKP + c4] = *(uint4*)t4;
        cvt4(t4, uv0); *(uint4*)&Bus[lr * BKP + c4]        = *(uint4*)t4;
        cvt4(t4, uv1); *(uint4*)&Bus[(lr + 32) * BKP + c4] = *(uint4*)t4;
        __syncthreads();

        int g  = lane >> 2;
        int tq = lane & 3;
#pragma unroll
        for (int kk = 0; kk < 4; kk++) {
            int kc = kk * 8 + tq;
            unsigned a[2][4];
#pragma unroll
            for (int mi = 0; mi < 2; mi++) {
                int r = wM * 32 + mi * 16 + g;
                a[mi][0] = As[r * BKP + kc];
                a[mi][1] = As[(r + 8) * BKP + kc];
                a[mi][2] = As[r * BKP + kc + 4];
                a[mi][3] = As[(r + 8) * BKP + kc + 4];
            }
#pragma unroll
            for (int ni = 0; ni < 4; ni++) {
                int br = wN * 32 + ni * 8 + g;
                unsigned bg0 = Bgs[br * BKP + kc];
                unsigned bg1 = Bgs[br * BKP + kc + 4];
                unsigned bu0 = Bus[br * BKP + kc];
                unsigned bu1 = Bus[br * BKP + kc + 4];
#pragma unroll
                for (int mi = 0; mi < 2; mi++) {
                    mma_tf32(cg[mi][ni], a[mi][0], a[mi][1], a[mi][2], a[mi][3], bg0, bg1);
                    mma_tf32(cu[mi][ni], a[mi][0], a[mi][1], a[mi][2], a[mi][3], bu0, bu1);
                }
            }
        }
    }

    // ---- epilogue ----
    int off = g_off[e];
    int g  = lane >> 2;
    int tq = lane & 3;
#pragma unroll
    for (int mi = 0; mi < 2; mi++) {
        int r0 = m0 + wM * 32 + mi * 16 + g;
        int r1 = r0 + 8;
        float w0 = (r0 < n) ? g_list_w[e * T_TOK + r0] : 0.f;
        float w1 = (r1 < n) ? g_list_w[e * T_TOK + r1] : 0.f;
#pragma unroll
        for (int ni = 0; ni < 4; ni++) {
            int col = c0 + wN * 32 + ni * 8 + 2 * tq;
            if (r0 < n) {
                float2 o;
                o.x = silu_f(cg[mi][ni][0]) * cu[mi][ni][0] * w0;
                o.y = silu_f(cg[mi][ni][1]) * cu[mi][ni][1] * w0;
                *(float2*)&g_act[((size_t)(off + r0)) * I_DIM + col] = o;
            }
            if (r1 < n) {
                float2 o;
                o.x = silu_f(cg[mi][ni][2]) * cu[mi][ni][2] * w1;
                o.y = silu_f(cg[mi][ni][3]) * cu[mi][ni][3] * w1;
                *(float2*)&g_act[((size_t)(off + r1)) * I_DIM + col] = o;
            }
        }
    }
}

// ---------------- grouped down-proj GEMM (tf32 mma) ----------------
__global__ __launch_bounds__(256) void down_kernel(const float* __restrict__ dw) {
    int e  = blockIdx.z;
    int n  = g_cnt[e];
    int m0 = blockIdx.x * BM;
    if (m0 >= n) return;
    int c0  = blockIdx.y * BN;
    int off = g_off[e];

    __shared__ unsigned As[BM * BKP];
    __shared__ unsigned Bs[BN * BKP];

    int tid  = threadIdx.x;
    int lane = tid & 31;
    int warp = tid >> 5;
    int wM = warp & 3;
    int wN = warp >> 2;

    int lr = tid >> 3;
    int c4 = (tid & 7) << 2;

    const float* aptr[4];
#pragma unroll
    for (int i = 0; i < 4; i++) {
        int row = off + min(m0 + lr + i * 32, n - 1);
        aptr[i] = g_act + (size_t)row * I_DIM + c4;
    }
    const float* bptr0 = dw + ((size_t)e * H_DIM + (c0 + lr)) * I_DIM + c4;
    const float* bptr1 = dw + ((size_t)e * H_DIM + (c0 + lr + 32)) * I_DIM + c4;

    float c[2][4][4] = {};

    for (int k0 = 0; k0 < I_DIM; k0 += BK) {
        float4 av[4];
#pragma unroll
        for (int i = 0; i < 4; i++) av[i] = *(const float4*)(aptr[i] + k0);
        float4 bv0 = *(const float4*)(bptr0 + k0);
        float4 bv1 = *(const float4*)(bptr1 + k0);

        __syncthreads();
        unsigned t4[4];
#pragma unroll
        for (int i = 0; i < 4; i++) {
            cvt4(t4, av[i]);
            *(uint4*)&As[(lr + i * 32) * BKP + c4] = *(uint4*)t4;
        }
        cvt4(t4, bv0); *(uint4*)&Bs[lr * BKP + c4]        = *(uint4*)t4;
        cvt4(t4, bv1); *(uint4*)&Bs[(lr + 32) * BKP + c4] = *(uint4*)t4;
        __syncthreads();

        int g  = lane >> 2;
        int tq = lane & 3;
#pragma unroll
        for (int kk = 0; kk < 4; kk++) {
            int kc = kk * 8 + tq;
            unsigned a[2][4];
#pragma unroll
            for (int mi = 0; mi < 2; mi++) {
                int r = wM * 32 + mi * 16 + g;
                a[mi][0] = As[r * BKP + kc];
                a[mi][1] = As[(r + 8) * BKP + kc];
                a[mi][2] = As[r * BKP + kc + 4];
                a[mi][3] = As[(r + 8) * BKP + kc + 4];
            }
#pragma unroll
            for (int ni = 0; ni < 4; ni++) {
                int br = wN * 32 + ni * 8 + g;
                unsigned b0 = Bs[br * BKP + kc];
                unsigned b1 = Bs[br * BKP + kc + 4];
#pragma unroll
                for (int mi = 0; mi < 2; mi++)
                    mma_tf32(c[mi][ni], a[mi][0], a[mi][1], a[mi][2], a[mi][3], b0, b1);
            }
        }
    }

    int g  = lane >> 2;
    int tq = lane & 3;
#pragma unroll
    for (int mi = 0; mi < 2; mi++) {
        int r0 = m0 + wM * 32 + mi * 16 + g;
        int r1 = r0 + 8;
#pragma unroll
        for (int ni = 0; ni < 4; ni++) {
            int col = c0 + wN * 32 + ni * 8 + 2 * tq;
            if (r0 < n) {
                float2 o = make_float2(c[mi][ni][0], c[mi][ni][1]);
                *(float2*)&g_pair[((size_t)(off + r0)) * H_DIM + col] = o;
            }
            if (r1 < n) {
                float2 o = make_float2(c[mi][ni][2], c[mi][ni][3]);
                *(float2*)&g_pair[((size_t)(off + r1)) * H_DIM + col] = o;
            }
        }
    }
}

// ---------------- per-token reduction ----------------
__global__ void reduce_kernel(float* __restrict__ out) {
    int t = blockIdx.x;
    int s[K_TOP];
#pragma unroll
    for (int k = 0; k < K_TOP; k++) s[k] = g_slot_of[t * K_TOP + k];
    const float4* base = (const float4*)g_pair;
    float4* ob = (float4*)(out + (size_t)t * H_DIM);
    for (int i = threadIdx.x; i < H_DIM / 4; i += blockDim.x) {
        float4 acc = make_float4(0.f, 0.f, 0.f, 0.f);
#pragma unroll
        for (int k = 0; k < K_TOP; k++) {
            float4 v = base[(size_t)s[k] * (H_DIM / 4) + i];
            acc.x += v.x; acc.y += v.y; acc.z += v.z; acc.w += v.w;
        }
        ob[i] = acc;
    }
}

// ---------------- launch ----------------
extern "C" void kernel_launch(void* const* d_in, const int* in_sizes, int n_in,
                              void* d_out, int out_size) {
    const float* x      = (const float*)d_in[0];
    const float* gate_w = (const float*)d_in[1];
    const float* gw     = (const float*)d_in[2];
    const float* uw     = (const float*)d_in[3];
    const float* dw     = (const float*)d_in[4];
    float* out = (float*)d_out;

    float* logits = (out_size >= T_TOK * H_DIM + T_TOK * E_NUM) ? (out + (size_t)T_TOK * H_DIM)
                                                                : (float*)0;

    zero_cnt_kernel<<<1, 32>>>();
    router_kernel<<<T_TOK / 4, 256>>>(x, gate_w, logits);
    scan_kernel<<<1, 32>>>();
    remap_kernel<<<E_NUM, 256>>>();
    gateup_kernel<<<dim3(T_TOK / BM, I_DIM / BN, E_NUM), 256>>>(x, gw, uw);
    down_kernel<<<dim3(T_TOK / BM, H_DIM / BN, E_NUM), 256>>>(dw);
    reduce_kernel<<<T_TOK, 256>>>(out);
}